// round 1
// baseline (speedup 1.0000x reference)
#include <cuda_runtime.h>
#include <cstdint>

#define N_NODES 50000
#define N_EDGES 800000

// Scratch (allocation-free rule: __device__ globals)
__device__ float g_bufA[(size_t)N_NODES * 128];
__device__ float g_bufB[(size_t)N_NODES * 128];
__device__ float g_agg [(size_t)N_NODES * 128];
__device__ float g_deg [N_NODES];
__device__ float g_inv [N_NODES];

// ---------------------------------------------------------------------------
// small utility kernels
// ---------------------------------------------------------------------------
__global__ void k_deg_zero() {
    int i = blockIdx.x * blockDim.x + threadIdx.x;
    if (i < N_NODES) g_deg[i] = 0.0f;
}

__global__ void k_deg(const int* __restrict__ dst) {
    int e = blockIdx.x * blockDim.x + threadIdx.x;
    if (e < N_EDGES) atomicAdd(&g_deg[dst[e]], 1.0f);
}

__global__ void k_inv_deg() {
    int i = blockIdx.x * blockDim.x + threadIdx.x;
    if (i < N_NODES) g_inv[i] = 1.0f / fmaxf(g_deg[i], 1.0f);
}

__global__ void k_zero_agg(int n4) {
    int i = blockIdx.x * blockDim.x + threadIdx.x;
    if (i < n4) reinterpret_cast<float4*>(g_agg)[i] = make_float4(0.f, 0.f, 0.f, 0.f);
}

// ---------------------------------------------------------------------------
// scatter: agg[dst] += x[src]   (edge-parallel, float4 granularity)
// LG = log2(F/4): F=64 -> LG=4, F=128 -> LG=5
// ---------------------------------------------------------------------------
template <int LG>
__global__ void k_scatter(const float* __restrict__ x,
                          const int* __restrict__ src,
                          const int* __restrict__ dst) {
    constexpr int G = 1 << LG;      // float4 groups per row
    constexpr int F = G * 4;
    long long idx = (long long)blockIdx.x * blockDim.x + threadIdx.x;
    int e = (int)(idx >> LG);
    int g = (int)(idx & (G - 1));
    if (e >= N_EDGES) return;
    int s = src[e];
    int d = dst[e];
    float4 v = *reinterpret_cast<const float4*>(x + (size_t)s * F + g * 4);
    float* a = g_agg + (size_t)d * F + g * 4;
    atomicAdd(a + 0, v.x);
    atomicAdd(a + 1, v.y);
    atomicAdd(a + 2, v.z);
    atomicAdd(a + 3, v.w);
}

// ---------------------------------------------------------------------------
// layer: out[n] = relu( (agg[n]*inv[n] + x[n]) @ W^T + b )
// blockDim.x = F_OUT, block handles BN nodes.
// W in smem padded by +4 floats/row -> conflict-free float4 LDS.
// ---------------------------------------------------------------------------
template <int F_IN, int F_OUT, int BN>
__global__ void k_layer(const float* __restrict__ x,
                        const float* __restrict__ W,
                        const float* __restrict__ b,
                        float* __restrict__ out) {
    extern __shared__ float sm[];
    constexpr int WP = F_IN + 4;
    float* sW  = sm;                       // F_OUT * WP
    float* sIn = sm + F_OUT * WP;          // BN * F_IN
    const int t = threadIdx.x;             // 0..F_OUT-1

    // load W (padded)
    for (int i = t; i < F_OUT * F_IN; i += F_OUT) {
        int r = i / F_IN;
        int c = i - r * F_IN;
        sW[r * WP + c] = W[i];
    }
    // build input rows h = agg*inv + x
    const int node0 = blockIdx.x * BN;
    for (int i = t; i < BN * F_IN; i += F_OUT) {
        int bn = i / F_IN;
        int c  = i - bn * F_IN;
        int n  = node0 + bn;
        sIn[i] = g_agg[(size_t)n * F_IN + c] * g_inv[n] + x[(size_t)n * F_IN + c];
    }
    __syncthreads();

    float acc[BN];
#pragma unroll
    for (int bn = 0; bn < BN; bn++) acc[bn] = b[t];

    const float4* w4 = reinterpret_cast<const float4*>(sW + t * WP);
#pragma unroll 4
    for (int k4 = 0; k4 < F_IN / 4; k4++) {
        float4 w = w4[k4];
#pragma unroll
        for (int bn = 0; bn < BN; bn++) {
            float4 v = reinterpret_cast<const float4*>(sIn + bn * F_IN)[k4];
            acc[bn] += w.x * v.x + w.y * v.y + w.z * v.z + w.w * v.w;
        }
    }

#pragma unroll
    for (int bn = 0; bn < BN; bn++) {
        out[(size_t)(node0 + bn) * F_OUT + t] = fmaxf(acc[bn], 0.0f);
    }
}

// ---------------------------------------------------------------------------
// heads: emb copy + next_event (64) + classes (10), fused
// out layout: [emb 50000*64 | next 50000*64 | cls 50000*10]
// ---------------------------------------------------------------------------
__global__ void k_heads(const float* __restrict__ x3,
                        const float* __restrict__ Wp, const float* __restrict__ bp,
                        const float* __restrict__ Wc, const float* __restrict__ bc,
                        float* __restrict__ out) {
    constexpr int F = 64, NH = 74, BN = 8, WP = F + 4;
    __shared__ float sW[NH * WP];
    __shared__ float sB[NH];
    __shared__ float sIn[BN * F];
    const int t = threadIdx.x;  // 128 threads

    for (int i = t; i < 64 * F; i += 128) {
        int r = i / F, c = i - r * F;
        sW[r * WP + c] = Wp[i];
    }
    for (int i = t; i < 10 * F; i += 128) {
        int r = i / F, c = i - r * F;
        sW[(64 + r) * WP + c] = Wc[i];
    }
    if (t < 64) sB[t] = bp[t];
    else if (t < NH) sB[t] = bc[t - 64];

    const int node0 = blockIdx.x * BN;
    for (int i = t; i < BN * F; i += 128) sIn[i] = x3[(size_t)node0 * F + i];
    __syncthreads();

    // embeddings copy
    for (int i = t; i < BN * F; i += 128) out[(size_t)node0 * F + i] = sIn[i];

    if (t < NH) {
        float acc[BN];
#pragma unroll
        for (int bn = 0; bn < BN; bn++) acc[bn] = sB[t];
        const float4* w4 = reinterpret_cast<const float4*>(sW + t * WP);
#pragma unroll
        for (int k4 = 0; k4 < F / 4; k4++) {
            float4 w = w4[k4];
#pragma unroll
            for (int bn = 0; bn < BN; bn++) {
                float4 v = reinterpret_cast<const float4*>(sIn + bn * F)[k4];
                acc[bn] += w.x * v.x + w.y * v.y + w.z * v.z + w.w * v.w;
            }
        }
#pragma unroll
        for (int bn = 0; bn < BN; bn++) {
            int n = node0 + bn;
            if (t < 64)
                out[(size_t)N_NODES * 64 + (size_t)n * 64 + t] = acc[bn];
            else
                out[(size_t)N_NODES * 128 + (size_t)n * 10 + (t - 64)] = acc[bn];
        }
    }
}

// ---------------------------------------------------------------------------
extern "C" void kernel_launch(void* const* d_in, const int* in_sizes, int n_in,
                              void* d_out, int out_size) {
    const float* x  = (const float*)d_in[0];
    const int*   ei = (const int*)d_in[1];
    const int* src = ei;
    const int* dst = ei + N_EDGES;
    const float* W1 = (const float*)d_in[2];
    const float* b1 = (const float*)d_in[3];
    const float* W2 = (const float*)d_in[4];
    const float* b2 = (const float*)d_in[5];
    const float* W3 = (const float*)d_in[6];
    const float* b3 = (const float*)d_in[7];
    const float* Wp = (const float*)d_in[8];
    const float* bp = (const float*)d_in[9];
    const float* Wc = (const float*)d_in[10];
    const float* bc = (const float*)d_in[11];
    float* out = (float*)d_out;

    constexpr int BN = 8;
    constexpr int NB = N_NODES / BN;  // 6250

    constexpr int SMEM_L1 = (128 * (64 + 4)  + BN * 64)  * 4;  // 36864
    constexpr int SMEM_L2 = (128 * (128 + 4) + BN * 128) * 4;  // 71680 (>48K)
    constexpr int SMEM_L3 = (64  * (128 + 4) + BN * 128) * 4;  // 37888

    cudaFuncSetAttribute(k_layer<128, 128, BN>,
                         cudaFuncAttributeMaxDynamicSharedMemorySize, SMEM_L2);

    // degrees (once, reused by all 3 layers)
    k_deg_zero<<<(N_NODES + 255) / 256, 256>>>();
    k_deg<<<(N_EDGES + 255) / 256, 256>>>(dst);
    k_inv_deg<<<(N_NODES + 255) / 256, 256>>>();

    // ---- layer 1: 64 -> 128 ----
    {
        int n4 = N_NODES * 64 / 4;
        k_zero_agg<<<(n4 + 255) / 256, 256>>>(n4);
        long long nt = (long long)N_EDGES << 4;
        k_scatter<4><<<(unsigned)((nt + 255) / 256), 256>>>(x, src, dst);
        k_layer<64, 128, BN><<<NB, 128, SMEM_L1>>>(x, W1, b1, g_bufA);
    }
    // ---- layer 2: 128 -> 128 ----
    {
        int n4 = N_NODES * 128 / 4;
        k_zero_agg<<<(n4 + 255) / 256, 256>>>(n4);
        long long nt = (long long)N_EDGES << 5;
        k_scatter<5><<<(unsigned)((nt + 255) / 256), 256>>>(g_bufA, src, dst);
        k_layer<128, 128, BN><<<NB, 128, SMEM_L2>>>(g_bufA, W2, b2, g_bufB);
    }
    // ---- layer 3: 128 -> 64 ----
    {
        int n4 = N_NODES * 128 / 4;
        k_zero_agg<<<(n4 + 255) / 256, 256>>>(n4);
        long long nt = (long long)N_EDGES << 5;
        k_scatter<5><<<(unsigned)((nt + 255) / 256), 256>>>(g_bufB, src, dst);
        k_layer<128, 64, BN><<<NB, 64, SMEM_L3>>>(g_bufB, W3, b3, g_bufA);
    }
    // ---- heads ----
    k_heads<<<NB, 128>>>(g_bufA, Wp, bp, Wc, bc, out);
}